// round 6
// baseline (speedup 1.0000x reference)
#include <cuda_runtime.h>
#include <cuda_fp16.h>
#include <cstdint>

// Problem constants (fixed: B=8, T=2048, D=2048)
#define B_SZ 8
#define T_SZ 2048
#define D_SZ 2048
#define M_SZ (B_SZ * T_SZ)        // 16384
#define CH_SZ (B_SZ * D_SZ)       // 16384 channels
#define SEG_LEN 256
#define N_SEG (T_SZ / SEG_LEN)    // 8

// ---------------- device scratch (static: no runtime allocation) ------------
__device__ __half g_xh[(size_t)M_SZ * D_SZ];     // fp16(x)
__device__ __half g_wh[(size_t)3 * D_SZ * D_SZ]; // fp16(W) for Wk,Wv,Wr
__device__ float g_k[(size_t)M_SZ * D_SZ];
__device__ float g_v[(size_t)M_SZ * D_SZ];
__device__ float g_r[(size_t)M_SZ * D_SZ];
__device__ float g_cn[(size_t)N_SEG * CH_SZ];
__device__ float g_cd[(size_t)N_SEG * CH_SZ];

// ---------------- helpers -----------------------------------------------------
__device__ __forceinline__ uint32_t smem_u32(const void* p) {
    uint32_t a;
    asm("{ .reg .u64 t; cvta.to.shared.u64 t, %1; cvt.u32.u64 %0, t; }" : "=r"(a) : "l"(p));
    return a;
}
__device__ __forceinline__ void cp16(uint32_t dst, const void* src) {
    asm volatile("cp.async.cg.shared.global [%0], [%1], 16;" :: "r"(dst), "l"(src));
}
// zfill variant: src_sz = 0 -> write 16 zero bytes
__device__ __forceinline__ void cp16z(uint32_t dst, const void* src, uint32_t src_sz) {
    asm volatile("cp.async.cg.shared.global [%0], [%1], 16, %2;"
                 :: "r"(dst), "l"(src), "r"(src_sz));
}
#define SWZ128(o) ((o) ^ (((o) >> 3) & 0x70))

__device__ __forceinline__ void ldsm_x4(uint32_t* r, uint32_t addr) {
    asm volatile("ldmatrix.sync.aligned.m8n8.x4.shared.b16 {%0,%1,%2,%3}, [%4];"
                 : "=r"(r[0]), "=r"(r[1]), "=r"(r[2]), "=r"(r[3]) : "r"(addr));
}
__device__ __forceinline__ void mma16816(float* c, const uint32_t* a, const uint32_t* b) {
    asm volatile(
        "mma.sync.aligned.m16n8k16.row.col.f32.f16.f16.f32 "
        "{%0,%1,%2,%3}, {%4,%5,%6,%7}, {%8,%9}, {%0,%1,%2,%3};"
        : "+f"(c[0]), "+f"(c[1]), "+f"(c[2]), "+f"(c[3])
        : "r"(a[0]), "r"(a[1]), "r"(a[2]), "r"(a[3]), "r"(b[0]), "r"(b[1]));
}

// ---------------- conversion: fp32 -> fp16 -------------------------------------
__global__ void convert_x_kernel(const float* __restrict__ x) {
    size_t i4 = (size_t)blockIdx.x * blockDim.x + threadIdx.x;
    if (i4 >= (size_t)M_SZ * D_SZ / 4) return;
    size_t i = i4 * 4;
    float4 v = *(const float4*)(x + i);
    __half2* hp = (__half2*)(g_xh + i);
    hp[0] = __halves2half2(__float2half_rn(v.x), __float2half_rn(v.y));
    hp[1] = __halves2half2(__float2half_rn(v.z), __float2half_rn(v.w));
}

__global__ void convert_w_kernel(const float* __restrict__ Wk,
                                 const float* __restrict__ Wv,
                                 const float* __restrict__ Wr) {
    const int z = blockIdx.y;
    const float* W = (z == 0) ? Wk : (z == 1) ? Wv : Wr;
    size_t i4 = (size_t)blockIdx.x * blockDim.x + threadIdx.x;
    if (i4 >= (size_t)D_SZ * D_SZ / 4) return;
    size_t i = i4 * 4;
    float4 v = *(const float4*)(W + i);
    __half2* op = (__half2*)(g_wh + (size_t)z * D_SZ * D_SZ + i);
    op[0] = __halves2half2(__float2half_rn(v.x), __float2half_rn(v.y));
    op[1] = __halves2half2(__float2half_rn(v.z), __float2half_rn(v.w));
}

// ---------------- HMMA GEMM: C[m,n] = sum_k A[m,k]*W[n,k] ---------------------
// Single fp16 MMA pass. Time shift read-side (zfill at t==0).
// Tile 128x256, warp tile 64x64 (8 warps, 2x4), BK=64, 4-stage cp.async, 1 CTA/SM.
#define BM 128
#define BN 256
#define BK 64
#define N_CHUNK (D_SZ / BK)        // 32
#define A_TILE_B 16384             // 128 rows x 128B
#define B_TILE_B 32768             // 256 rows x 128B
#define STAGE_BYTES (A_TILE_B + B_TILE_B)   // 48 KB
#define N_STAGE 4
#define GEMM_SMEM (N_STAGE * STAGE_BYTES)   // 192 KB

__global__ __launch_bounds__(256, 1)
void gemm_hmma_kernel() {
    extern __shared__ char smem[];
    const uint32_t sbase = smem_u32(smem);
    const int tid = threadIdx.x;
    const int wid = tid >> 5;
    const int lane = tid & 31;
    const int wm = wid & 1;          // 2 warps over M (64 each)
    const int wn = wid >> 1;         // 4 warps over N (64 each)

    const int z = blockIdx.z;
    const int m0 = blockIdx.y * BM;
    const int n0 = blockIdx.x * BN;
    const bool shift = (z < 2);

    const __half* B_h = g_wh + (size_t)z * D_SZ * D_SZ;
    float* C = (z == 0) ? g_k : (z == 1) ? g_v : g_r;

    float acc[4][8][4];
#pragma unroll
    for (int i = 0; i < 4; i++)
#pragma unroll
        for (int j = 0; j < 8; j++)
#pragma unroll
            for (int q = 0; q < 4; q++) acc[i][j][q] = 0.f;

    // stage loader: K-chunk c into stage s. 3072 16B lines / 256 thr = 12 each.
    auto load_stage = [&](int c, int s) {
        const int kt = c * BK;
        const uint32_t st = sbase + s * STAGE_BYTES;
        // A: 1024 lines
#pragma unroll
        for (int it = 0; it < 4; it++) {
            const int i = tid + it * 256;
            const int row = i >> 3, seg = i & 7;
            const uint32_t sw = SWZ128((uint32_t)(row * 128 + seg * 16));
            const int rm = m0 + row;
            uint32_t sz = 16;
            int srow = rm;
            if (shift) {
                if ((rm & (T_SZ - 1)) == 0) sz = 0;
                else srow = rm - 1;
            }
            cp16z(st + sw, g_xh + (size_t)srow * D_SZ + kt + seg * 8, sz);
        }
        // B: 2048 lines
#pragma unroll
        for (int it = 0; it < 8; it++) {
            const int i = tid + it * 256;
            const int row = i >> 3, seg = i & 7;
            const uint32_t sw = SWZ128((uint32_t)(row * 128 + seg * 16));
            cp16(st + A_TILE_B + sw, B_h + (size_t)(n0 + row) * D_SZ + kt + seg * 8);
        }
        asm volatile("cp.async.commit_group;" ::: "memory");
    };

    load_stage(0, 0);
    load_stage(1, 1);
    load_stage(2, 2);
    load_stage(3, 3);

    const int a_row = lane & 15;
    const int a_half = lane >> 4;
    const int b_nr = (lane & 7) + ((lane >> 4) << 3);
    const int b_half = (lane >> 3) & 1;

    int s = 0;
    for (int c = 0; c < N_CHUNK; c++) {
        const int remaining = N_CHUNK - 1 - c;   // chunks after this one
        if (remaining >= 3)      asm volatile("cp.async.wait_group 3;" ::: "memory");
        else if (remaining == 2) asm volatile("cp.async.wait_group 2;" ::: "memory");
        else if (remaining == 1) asm volatile("cp.async.wait_group 1;" ::: "memory");
        else                     asm volatile("cp.async.wait_group 0;" ::: "memory");
        __syncthreads();

        const uint32_t sA = sbase + s * STAGE_BYTES;
        const uint32_t sB = sA + A_TILE_B;

#pragma unroll
        for (int ks = 0; ks < 4; ks++) {
            uint32_t aa[4][4], bb[4][4];
#pragma unroll
            for (int mi = 0; mi < 4; mi++) {
                const uint32_t off = SWZ128(
                    (uint32_t)((wm * 64 + mi * 16 + a_row) * 128 + ks * 32 + a_half * 16));
                ldsm_x4(aa[mi], sA + off);
            }
#pragma unroll
            for (int j = 0; j < 4; j++) {
                const uint32_t off = SWZ128(
                    (uint32_t)((wn * 64 + j * 16 + b_nr) * 128 + ks * 32 + b_half * 16));
                ldsm_x4(bb[j], sB + off);
            }
#pragma unroll
            for (int mi = 0; mi < 4; mi++)
#pragma unroll
                for (int ni = 0; ni < 8; ni++)
                    mma16816(acc[mi][ni], aa[mi], &bb[ni >> 1][(ni & 1) * 2]);
        }
        __syncthreads();
        if (c + N_STAGE < N_CHUNK) load_stage(c + N_STAGE, s);
        s = (s == N_STAGE - 1) ? 0 : s + 1;
    }

    // epilogue
#pragma unroll
    for (int mi = 0; mi < 4; mi++) {
        const int gm = m0 + wm * 64 + mi * 16 + (lane >> 2);
#pragma unroll
        for (int ni = 0; ni < 8; ni++) {
            const int gn = n0 + wn * 64 + ni * 8 + (lane & 3) * 2;
            float* p0 = C + (size_t)gm * D_SZ + gn;
            float* p1 = p0 + 8 * D_SZ;
            *(float2*)p0 = make_float2(acc[mi][ni][0], acc[mi][ni][1]);
            *(float2*)p1 = make_float2(acc[mi][ni][2], acc[mi][ni][3]);
        }
    }
}

// ---------------- split WKV scan ------------------------------------------------
__global__ void wkv_p1_kernel(const float* __restrict__ time_decay) {
    const int gid = blockIdx.x * blockDim.x + threadIdx.x;
    const int c = gid & (CH_SZ - 1);
    const int seg = gid >> 14;
    const int d = c & (D_SZ - 1);
    const int b = c >> 11;
    const float w = expf(-expf(time_decay[d]));

    const size_t base = (size_t)b * T_SZ * D_SZ + (size_t)seg * SEG_LEN * D_SZ + d;
    const float* kp = g_k + base;
    const float* vp = g_v + base;

    float num = 0.f, den = 0.f;
    for (int t = 0; t < SEG_LEN; t += 8) {
        float kk[8], vv[8];
#pragma unroll
        for (int i = 0; i < 8; i++) {
            const size_t o = (size_t)(t + i) * D_SZ;
            kk[i] = kp[o]; vv[i] = vp[o];
        }
#pragma unroll
        for (int i = 0; i < 8; i++) {
            const float ek = expf(kk[i]);
            num = fmaf(w, num, ek * vv[i]);
            den = fmaf(w, den, ek);
        }
    }
    g_cn[gid] = num;
    g_cd[gid] = den;
}

__global__ void wkv_p2_kernel(const float* __restrict__ time_decay,
                              const float* __restrict__ x,
                              float* __restrict__ out) {
    const int gid = blockIdx.x * blockDim.x + threadIdx.x;
    const int c = gid & (CH_SZ - 1);
    const int seg = gid >> 14;
    const int d = c & (D_SZ - 1);
    const int b = c >> 11;

    const float e = expf(time_decay[d]);
    const float w = expf(-e);
    const float wl = expf(-(float)SEG_LEN * e);   // w^SEG_LEN

    float num = 0.f, den = 0.f;
    for (int i = 0; i < seg; i++) {
        num = fmaf(wl, num, g_cn[i * CH_SZ + c]);
        den = fmaf(wl, den, g_cd[i * CH_SZ + c]);
    }

    const size_t base = (size_t)b * T_SZ * D_SZ + (size_t)seg * SEG_LEN * D_SZ + d;
    const float* kp = g_k + base;
    const float* vp = g_v + base;
    const float* rp = g_r + base;
    float* op = out + base;

    for (int t = 0; t < SEG_LEN; t += 8) {
        float kk[8], vv[8], rr[8];
#pragma unroll
        for (int i = 0; i < 8; i++) {
            const size_t o = (size_t)(t + i) * D_SZ;
            kk[i] = kp[o]; vv[i] = vp[o]; rr[i] = rp[o];
        }
#pragma unroll
        for (int i = 0; i < 8; i++) {
            const float ek = expf(kk[i]);
            num = fmaf(w, num, ek * vv[i]);
            den = fmaf(w, den, ek);
            op[(size_t)(t + i) * D_SZ] = rr[i] * num / (den + 1e-8f);
        }
    }

    if (seg == 0) {
        float* out2 = out + (size_t)B_SZ * T_SZ * D_SZ;
        out2[c] = x[(size_t)b * T_SZ * D_SZ + (size_t)(T_SZ - 2) * D_SZ + d];
    }
}

// ---------------- launch --------------------------------------------------------
extern "C" void kernel_launch(void* const* d_in, const int* in_sizes, int n_in,
                              void* d_out, int out_size)
{
    const float* x  = (const float*)d_in[0];
    const float* Wk = (const float*)d_in[1];
    const float* Wv = (const float*)d_in[2];
    const float* Wr = (const float*)d_in[3];
    const float* td = (const float*)d_in[4];
    float* out = (float*)d_out;

    cudaFuncSetAttribute(gemm_hmma_kernel,
                         cudaFuncAttributeMaxDynamicSharedMemorySize, GEMM_SMEM);

    convert_x_kernel<<<(M_SZ * (size_t)D_SZ / 4 + 255) / 256, 256>>>(x);
    {
        dim3 g((D_SZ * (size_t)D_SZ / 4 + 255) / 256, 3);
        convert_w_kernel<<<g, 256>>>(Wk, Wv, Wr);
    }

    dim3 gg(D_SZ / BN, M_SZ / BM, 3);   // (8, 128, 3)
    gemm_hmma_kernel<<<gg, 256, GEMM_SMEM>>>();

    const int total = N_SEG * CH_SZ;    // 131072
    wkv_p1_kernel<<<total / 256, 256>>>(td);
    wkv_p2_kernel<<<total / 256, 256>>>(td, x, out);
}